// round 3
// baseline (speedup 1.0000x reference)
#include <cuda_runtime.h>

#define B_  4
#define C_  64
#define N_  4096
#define CK  32       // f/g channel count
#define MT  64       // rows (query pixels) per CTA
#define NT  64       // key tile width

// Scratch for projected tensors (bss, no allocation)
__device__ float g_fbuf[B_ * CK * N_];
__device__ float g_gbuf[B_ * CK * N_];
__device__ float g_hbuf[B_ * C_ * N_];

// ---------------------------------------------------------------------------
// Projection: out[b, oc0+o, n] = sum_c W[oc0+o, c] * in[b, c, n] + bias[oc0+o]
// grid.x covers B*N / 256 pixels, grid.y covers output channels in chunks of 16
// ---------------------------------------------------------------------------
__global__ __launch_bounds__(256) void proj_kernel(
    const float* __restrict__ W, const float* __restrict__ bias,
    const float* __restrict__ in, float* __restrict__ out, int OC)
{
    __shared__ float Ws[16][64];
    const int oc0 = blockIdx.y * 16;
    const int t = threadIdx.x;
    for (int i = t; i < 16 * 64; i += 256)
        Ws[i >> 6][i & 63] = W[(oc0 + (i >> 6)) * C_ + (i & 63)];
    __syncthreads();

    const int pix = blockIdx.x * 256 + t;        // 0 .. B*N-1
    const int b = pix >> 12;                      // / 4096
    const int n = pix & (N_ - 1);
    const float* inp = in + (size_t)b * C_ * N_ + n;

    float acc[16];
#pragma unroll
    for (int o = 0; o < 16; o++) acc[o] = bias[oc0 + o];

#pragma unroll 4
    for (int c = 0; c < C_; c++) {
        float v = inp[(size_t)c * N_];
#pragma unroll
        for (int o = 0; o < 16; o++) acc[o] = fmaf(Ws[o][c], v, acc[o]);
    }

    float* op = out + (size_t)b * OC * N_ + (size_t)oc0 * N_ + n;
#pragma unroll
    for (int o = 0; o < 16; o++) op[(size_t)o * N_] = acc[o];
}

// ---------------------------------------------------------------------------
// Fused flash-attention: per CTA = (batch b, 64-row query block m0)
//   S[m,n] = sum_c g[c,m]*f[c,n];  beta = softmax_n(S);  O[m,c] = sum_n beta*h[c,n]
//   out[b,c,m] = gamma * O[m,c] + x[b,c,m]
// 256 threads, thread (ty,tx) owns 4x4 register tile: rows ty*4.., cols tx*4..
// ---------------------------------------------------------------------------
__global__ __launch_bounds__(256, 2) void attn_kernel(
    const float* __restrict__ x, const float* __restrict__ gamma_p,
    float* __restrict__ out)
{
    __shared__ float gT[MT][CK + 4];   // [m][c]
    __shared__ float fS[CK][NT + 4];   // [c][n]
    __shared__ float hS[C_][NT + 4];   // [c][n]
    __shared__ float pS[MT][NT + 4];   // [m][n]

    const int b  = blockIdx.y;
    const int m0 = blockIdx.x * MT;
    const int t  = threadIdx.x;
    const int ty = t >> 4, tx = t & 15;
    const int r0 = ty * 4;             // local row base (m)
    const int c0 = tx * 4;             // local col base (n in S, channel in O)

    const float* fb = g_fbuf + (size_t)b * CK * N_;
    const float* gb = g_gbuf + (size_t)b * CK * N_;
    const float* hb = g_hbuf + (size_t)b * C_ * N_;

    // load g^T block once: gT[m][c] = g[c][m0+m]
    for (int v = t; v < MT * CK; v += 256) {
        int m = v & (MT - 1), c = v >> 6;
        gT[m][c] = gb[(size_t)c * N_ + m0 + m];
    }

    float mi[4], li[4], acc[4][4];
#pragma unroll
    for (int i = 0; i < 4; i++) {
        mi[i] = -1e30f; li[i] = 0.f;
#pragma unroll
        for (int j = 0; j < 4; j++) acc[i][j] = 0.f;
    }

    for (int n0 = 0; n0 < N_; n0 += NT) {
        // ---- load f/h tiles (float4, coalesced) ----
        for (int v = t; v < CK * (NT / 4); v += 256) {      // 512 float4 / 256 thr
            int c = v >> 4, q = (v & 15) * 4;
            *(float4*)&fS[c][q] = *(const float4*)&fb[(size_t)c * N_ + n0 + q];
        }
        for (int v = t; v < C_ * (NT / 4); v += 256) {      // 1024 float4
            int c = v >> 4, q = (v & 15) * 4;
            *(float4*)&hS[c][q] = *(const float4*)&hb[(size_t)c * N_ + n0 + q];
        }
        __syncthreads();

        // ---- S = g^T f  (64x64 tile, K=32) ----
        float s[4][4];
#pragma unroll
        for (int i = 0; i < 4; i++)
#pragma unroll
            for (int j = 0; j < 4; j++) s[i][j] = 0.f;

#pragma unroll 4
        for (int c = 0; c < CK; c += 4) {
            float4 bq0 = *(const float4*)&fS[c + 0][c0];
            float4 bq1 = *(const float4*)&fS[c + 1][c0];
            float4 bq2 = *(const float4*)&fS[c + 2][c0];
            float4 bq3 = *(const float4*)&fS[c + 3][c0];
            float br0[4] = {bq0.x, bq0.y, bq0.z, bq0.w};
            float br1[4] = {bq1.x, bq1.y, bq1.z, bq1.w};
            float br2[4] = {bq2.x, bq2.y, bq2.z, bq2.w};
            float br3[4] = {bq3.x, bq3.y, bq3.z, bq3.w};
#pragma unroll
            for (int i = 0; i < 4; i++) {
                float4 aq = *(const float4*)&gT[r0 + i][c];
#pragma unroll
                for (int j = 0; j < 4; j++) {
                    s[i][j] = fmaf(aq.x, br0[j], s[i][j]);
                    s[i][j] = fmaf(aq.y, br1[j], s[i][j]);
                    s[i][j] = fmaf(aq.z, br2[j], s[i][j]);
                    s[i][j] = fmaf(aq.w, br3[j], s[i][j]);
                }
            }
        }

        // ---- online softmax ----
#pragma unroll
        for (int i = 0; i < 4; i++) {
            float mt = fmaxf(fmaxf(s[i][0], s[i][1]), fmaxf(s[i][2], s[i][3]));
#pragma unroll
            for (int k = 1; k < 16; k <<= 1)
                mt = fmaxf(mt, __shfl_xor_sync(0xffffffffu, mt, k));
            float mn = fmaxf(mi[i], mt);
            float sc = __expf(mi[i] - mn);
            mi[i] = mn;
            float p0 = __expf(s[i][0] - mn);
            float p1 = __expf(s[i][1] - mn);
            float p2 = __expf(s[i][2] - mn);
            float p3 = __expf(s[i][3] - mn);
            s[i][0] = p0; s[i][1] = p1; s[i][2] = p2; s[i][3] = p3;
            float ls = (p0 + p1) + (p2 + p3);
#pragma unroll
            for (int k = 1; k < 16; k <<= 1)
                ls += __shfl_xor_sync(0xffffffffu, ls, k);
            li[i] = li[i] * sc + ls;
#pragma unroll
            for (int j = 0; j < 4; j++) acc[i][j] *= sc;
        }

        // ---- stage P to smem ----
#pragma unroll
        for (int i = 0; i < 4; i++)
            *(float4*)&pS[r0 + i][c0] = make_float4(s[i][0], s[i][1], s[i][2], s[i][3]);
        __syncthreads();

        // ---- O += P @ h^T  (K=64) ----
#pragma unroll 4
        for (int n = 0; n < NT; n += 4) {
            float4 hq0 = *(const float4*)&hS[c0 + 0][n];
            float4 hq1 = *(const float4*)&hS[c0 + 1][n];
            float4 hq2 = *(const float4*)&hS[c0 + 2][n];
            float4 hq3 = *(const float4*)&hS[c0 + 3][n];
#pragma unroll
            for (int i = 0; i < 4; i++) {
                float4 pq = *(const float4*)&pS[r0 + i][n];
                acc[i][0] = fmaf(pq.x, hq0.x, acc[i][0]);
                acc[i][0] = fmaf(pq.y, hq0.y, acc[i][0]);
                acc[i][0] = fmaf(pq.z, hq0.z, acc[i][0]);
                acc[i][0] = fmaf(pq.w, hq0.w, acc[i][0]);
                acc[i][1] = fmaf(pq.x, hq1.x, acc[i][1]);
                acc[i][1] = fmaf(pq.y, hq1.y, acc[i][1]);
                acc[i][1] = fmaf(pq.z, hq1.z, acc[i][1]);
                acc[i][1] = fmaf(pq.w, hq1.w, acc[i][1]);
                acc[i][2] = fmaf(pq.x, hq2.x, acc[i][2]);
                acc[i][2] = fmaf(pq.y, hq2.y, acc[i][2]);
                acc[i][2] = fmaf(pq.z, hq2.z, acc[i][2]);
                acc[i][2] = fmaf(pq.w, hq2.w, acc[i][2]);
                acc[i][3] = fmaf(pq.x, hq3.x, acc[i][3]);
                acc[i][3] = fmaf(pq.y, hq3.y, acc[i][3]);
                acc[i][3] = fmaf(pq.z, hq3.z, acc[i][3]);
                acc[i][3] = fmaf(pq.w, hq3.w, acc[i][3]);
            }
        }
        __syncthreads();
    }

    // ---- epilogue: out[b, c, m] = gamma * acc[m][c]/li[m] + x[b, c, m] ----
    const float gm = *gamma_p;
    float inv[4];
#pragma unroll
    for (int i = 0; i < 4; i++) inv[i] = 1.0f / li[i];

#pragma unroll
    for (int j = 0; j < 4; j++) {
        const int c = c0 + j;  // channel (0..63)
        const size_t base = (size_t)b * C_ * N_ + (size_t)c * N_ + m0 + r0;
        float4 xv = *(const float4*)&x[base];
        float4 ov;
        ov.x = fmaf(gm, acc[0][j] * inv[0], xv.x);
        ov.y = fmaf(gm, acc[1][j] * inv[1], xv.y);
        ov.z = fmaf(gm, acc[2][j] * inv[2], xv.z);
        ov.w = fmaf(gm, acc[3][j] * inv[3], xv.w);
        *(float4*)&out[base] = ov;
    }
}

// ---------------------------------------------------------------------------
extern "C" void kernel_launch(void* const* d_in, const int* in_sizes, int n_in,
                              void* d_out, int out_size)
{
    const float* x     = (const float*)d_in[0];
    const float* y     = (const float*)d_in[1];
    const float* Wf    = (const float*)d_in[2];
    const float* bf    = (const float*)d_in[3];
    const float* Wg    = (const float*)d_in[4];
    const float* bg    = (const float*)d_in[5];
    const float* Wh    = (const float*)d_in[6];
    const float* bh    = (const float*)d_in[7];
    const float* gamma = (const float*)d_in[8];
    float* out = (float*)d_out;

    float *fp, *gp, *hp;
    cudaGetSymbolAddress((void**)&fp, g_fbuf);
    cudaGetSymbolAddress((void**)&gp, g_gbuf);
    cudaGetSymbolAddress((void**)&hp, g_hbuf);

    dim3 pb(256);
    proj_kernel<<<dim3(B_ * N_ / 256, CK / 16), pb>>>(Wf, bf, x, fp, CK);
    proj_kernel<<<dim3(B_ * N_ / 256, CK / 16), pb>>>(Wg, bg, y, gp, CK);
    proj_kernel<<<dim3(B_ * N_ / 256, C_ / 16), pb>>>(Wh, bh, y, hp, C_);

    attn_kernel<<<dim3(N_ / MT, B_), 256>>>(x, gamma, out);
}

// round 4
// speedup vs baseline: 1.0018x; 1.0018x over previous
#include <cuda_runtime.h>

#define B_  4
#define C_  64
#define N_  4096
#define CK  32       // f/g channel count
#define MT  64       // rows (query pixels) per CTA
#define NT  64       // key tile width

// Scratch for projected tensors (bss, no allocation)
__device__ float g_fbuf[B_ * CK * N_];
__device__ float g_gbuf[B_ * CK * N_];
__device__ float g_hbuf[B_ * C_ * N_];

// ---------------------------------------------------------------------------
// Projection: out[b, oc0+o, n] = sum_c W[oc0+o, c] * in[b, c, n] + bias[oc0+o]
// grid.x covers B*N / 256 pixels, grid.y covers output channels in chunks of 16
// ---------------------------------------------------------------------------
__global__ __launch_bounds__(256) void proj_kernel(
    const float* __restrict__ W, const float* __restrict__ bias,
    const float* __restrict__ in, float* __restrict__ out, int OC)
{
    __shared__ float Ws[16][64];
    const int oc0 = blockIdx.y * 16;
    const int t = threadIdx.x;
    for (int i = t; i < 16 * 64; i += 256)
        Ws[i >> 6][i & 63] = W[(oc0 + (i >> 6)) * C_ + (i & 63)];
    __syncthreads();

    const int pix = blockIdx.x * 256 + t;        // 0 .. B*N-1
    const int b = pix >> 12;                      // / 4096
    const int n = pix & (N_ - 1);
    const float* inp = in + (size_t)b * C_ * N_ + n;

    float acc[16];
#pragma unroll
    for (int o = 0; o < 16; o++) acc[o] = bias[oc0 + o];

#pragma unroll 4
    for (int c = 0; c < C_; c++) {
        float v = inp[(size_t)c * N_];
#pragma unroll
        for (int o = 0; o < 16; o++) acc[o] = fmaf(Ws[o][c], v, acc[o]);
    }

    float* op = out + (size_t)b * OC * N_ + (size_t)oc0 * N_ + n;
#pragma unroll
    for (int o = 0; o < 16; o++) op[(size_t)o * N_] = acc[o];
}

// ---------------------------------------------------------------------------
// Fused flash-attention: per CTA = (batch b, 64-row query block m0)
//   S[m,n] = sum_c g[c,m]*f[c,n];  beta = softmax_n(S);  O[m,c] = sum_n beta*h[c,n]
//   out[b,c,m] = gamma * O[m,c] + x[b,c,m]
// 256 threads, thread (ty,tx) owns 4x4 register tile: rows ty*4.., cols tx*4..
// ---------------------------------------------------------------------------
__global__ __launch_bounds__(256, 2) void attn_kernel(
    const float* __restrict__ x, const float* __restrict__ gamma_p,
    float* __restrict__ out)
{
    __shared__ float gT[MT][CK + 4];   // [m][c]
    __shared__ float fS[CK][NT + 4];   // [c][n]
    __shared__ float hS[C_][NT + 4];   // [c][n]
    __shared__ float pS[MT][NT + 4];   // [m][n]

    const int b  = blockIdx.y;
    const int m0 = blockIdx.x * MT;
    const int t  = threadIdx.x;
    const int ty = t >> 4, tx = t & 15;
    const int r0 = ty * 4;             // local row base (m)
    const int c0 = tx * 4;             // local col base (n in S, channel in O)

    const float* fb = g_fbuf + (size_t)b * CK * N_;
    const float* gb = g_gbuf + (size_t)b * CK * N_;
    const float* hb = g_hbuf + (size_t)b * C_ * N_;

    // load g^T block once: gT[m][c] = g[c][m0+m]
    for (int v = t; v < MT * CK; v += 256) {
        int m = v & (MT - 1), c = v >> 6;
        gT[m][c] = gb[(size_t)c * N_ + m0 + m];
    }

    float mi[4], li[4], acc[4][4];
#pragma unroll
    for (int i = 0; i < 4; i++) {
        mi[i] = -1e30f; li[i] = 0.f;
#pragma unroll
        for (int j = 0; j < 4; j++) acc[i][j] = 0.f;
    }

    for (int n0 = 0; n0 < N_; n0 += NT) {
        // ---- load f/h tiles (float4, coalesced) ----
        for (int v = t; v < CK * (NT / 4); v += 256) {      // 512 float4 / 256 thr
            int c = v >> 4, q = (v & 15) * 4;
            *(float4*)&fS[c][q] = *(const float4*)&fb[(size_t)c * N_ + n0 + q];
        }
        for (int v = t; v < C_ * (NT / 4); v += 256) {      // 1024 float4
            int c = v >> 4, q = (v & 15) * 4;
            *(float4*)&hS[c][q] = *(const float4*)&hb[(size_t)c * N_ + n0 + q];
        }
        __syncthreads();

        // ---- S = g^T f  (64x64 tile, K=32) ----
        float s[4][4];
#pragma unroll
        for (int i = 0; i < 4; i++)
#pragma unroll
            for (int j = 0; j < 4; j++) s[i][j] = 0.f;

#pragma unroll 4
        for (int c = 0; c < CK; c += 4) {
            float4 bq0 = *(const float4*)&fS[c + 0][c0];
            float4 bq1 = *(const float4*)&fS[c + 1][c0];
            float4 bq2 = *(const float4*)&fS[c + 2][c0];
            float4 bq3 = *(const float4*)&fS[c + 3][c0];
            float br0[4] = {bq0.x, bq0.y, bq0.z, bq0.w};
            float br1[4] = {bq1.x, bq1.y, bq1.z, bq1.w};
            float br2[4] = {bq2.x, bq2.y, bq2.z, bq2.w};
            float br3[4] = {bq3.x, bq3.y, bq3.z, bq3.w};
#pragma unroll
            for (int i = 0; i < 4; i++) {
                float4 aq = *(const float4*)&gT[r0 + i][c];
#pragma unroll
                for (int j = 0; j < 4; j++) {
                    s[i][j] = fmaf(aq.x, br0[j], s[i][j]);
                    s[i][j] = fmaf(aq.y, br1[j], s[i][j]);
                    s[i][j] = fmaf(aq.z, br2[j], s[i][j]);
                    s[i][j] = fmaf(aq.w, br3[j], s[i][j]);
                }
            }
        }

        // ---- online softmax ----
#pragma unroll
        for (int i = 0; i < 4; i++) {
            float mt = fmaxf(fmaxf(s[i][0], s[i][1]), fmaxf(s[i][2], s[i][3]));
#pragma unroll
            for (int k = 1; k < 16; k <<= 1)
                mt = fmaxf(mt, __shfl_xor_sync(0xffffffffu, mt, k));
            float mn = fmaxf(mi[i], mt);
            float sc = __expf(mi[i] - mn);
            mi[i] = mn;
            float p0 = __expf(s[i][0] - mn);
            float p1 = __expf(s[i][1] - mn);
            float p2 = __expf(s[i][2] - mn);
            float p3 = __expf(s[i][3] - mn);
            s[i][0] = p0; s[i][1] = p1; s[i][2] = p2; s[i][3] = p3;
            float ls = (p0 + p1) + (p2 + p3);
#pragma unroll
            for (int k = 1; k < 16; k <<= 1)
                ls += __shfl_xor_sync(0xffffffffu, ls, k);
            li[i] = li[i] * sc + ls;
#pragma unroll
            for (int j = 0; j < 4; j++) acc[i][j] *= sc;
        }

        // ---- stage P to smem ----
#pragma unroll
        for (int i = 0; i < 4; i++)
            *(float4*)&pS[r0 + i][c0] = make_float4(s[i][0], s[i][1], s[i][2], s[i][3]);
        __syncthreads();

        // ---- O += P @ h^T  (K=64) ----
#pragma unroll 4
        for (int n = 0; n < NT; n += 4) {
            float4 hq0 = *(const float4*)&hS[c0 + 0][n];
            float4 hq1 = *(const float4*)&hS[c0 + 1][n];
            float4 hq2 = *(const float4*)&hS[c0 + 2][n];
            float4 hq3 = *(const float4*)&hS[c0 + 3][n];
#pragma unroll
            for (int i = 0; i < 4; i++) {
                float4 pq = *(const float4*)&pS[r0 + i][n];
                acc[i][0] = fmaf(pq.x, hq0.x, acc[i][0]);
                acc[i][0] = fmaf(pq.y, hq0.y, acc[i][0]);
                acc[i][0] = fmaf(pq.z, hq0.z, acc[i][0]);
                acc[i][0] = fmaf(pq.w, hq0.w, acc[i][0]);
                acc[i][1] = fmaf(pq.x, hq1.x, acc[i][1]);
                acc[i][1] = fmaf(pq.y, hq1.y, acc[i][1]);
                acc[i][1] = fmaf(pq.z, hq1.z, acc[i][1]);
                acc[i][1] = fmaf(pq.w, hq1.w, acc[i][1]);
                acc[i][2] = fmaf(pq.x, hq2.x, acc[i][2]);
                acc[i][2] = fmaf(pq.y, hq2.y, acc[i][2]);
                acc[i][2] = fmaf(pq.z, hq2.z, acc[i][2]);
                acc[i][2] = fmaf(pq.w, hq2.w, acc[i][2]);
                acc[i][3] = fmaf(pq.x, hq3.x, acc[i][3]);
                acc[i][3] = fmaf(pq.y, hq3.y, acc[i][3]);
                acc[i][3] = fmaf(pq.z, hq3.z, acc[i][3]);
                acc[i][3] = fmaf(pq.w, hq3.w, acc[i][3]);
            }
        }
        __syncthreads();
    }

    // ---- epilogue: out[b, c, m] = gamma * acc[m][c]/li[m] + x[b, c, m] ----
    const float gm = *gamma_p;
    float inv[4];
#pragma unroll
    for (int i = 0; i < 4; i++) inv[i] = 1.0f / li[i];

#pragma unroll
    for (int j = 0; j < 4; j++) {
        const int c = c0 + j;  // channel (0..63)
        const size_t base = (size_t)b * C_ * N_ + (size_t)c * N_ + m0 + r0;
        float4 xv = *(const float4*)&x[base];
        float4 ov;
        ov.x = fmaf(gm, acc[0][j] * inv[0], xv.x);
        ov.y = fmaf(gm, acc[1][j] * inv[1], xv.y);
        ov.z = fmaf(gm, acc[2][j] * inv[2], xv.z);
        ov.w = fmaf(gm, acc[3][j] * inv[3], xv.w);
        *(float4*)&out[base] = ov;
    }
}

// ---------------------------------------------------------------------------
extern "C" void kernel_launch(void* const* d_in, const int* in_sizes, int n_in,
                              void* d_out, int out_size)
{
    const float* x     = (const float*)d_in[0];
    const float* y     = (const float*)d_in[1];
    const float* Wf    = (const float*)d_in[2];
    const float* bf    = (const float*)d_in[3];
    const float* Wg    = (const float*)d_in[4];
    const float* bg    = (const float*)d_in[5];
    const float* Wh    = (const float*)d_in[6];
    const float* bh    = (const float*)d_in[7];
    const float* gamma = (const float*)d_in[8];
    float* out = (float*)d_out;

    float *fp, *gp, *hp;
    cudaGetSymbolAddress((void**)&fp, g_fbuf);
    cudaGetSymbolAddress((void**)&gp, g_gbuf);
    cudaGetSymbolAddress((void**)&hp, g_hbuf);

    dim3 pb(256);
    proj_kernel<<<dim3(B_ * N_ / 256, CK / 16), pb>>>(Wf, bf, x, fp, CK);
    proj_kernel<<<dim3(B_ * N_ / 256, CK / 16), pb>>>(Wg, bg, y, gp, CK);
    proj_kernel<<<dim3(B_ * N_ / 256, C_ / 16), pb>>>(Wh, bh, y, hp, C_);

    attn_kernel<<<dim3(N_ / MT, B_), 256>>>(x, gamma, out);
}